// round 1
// baseline (speedup 1.0000x reference)
#include <cuda_runtime.h>
#include <math.h>

#define Bm 64
#define Tm 256
#define DIN 512
#define Hm 1024
#define G4 4096
#define C_OUT 1000

// Scratch (device globals; no runtime allocation allowed)
__device__ float g_xg[(size_t)Bm * Tm * G4];    // 256 MB: precomputed input gates (reused per layer)
__device__ float g_hseq[(size_t)Bm * Tm * Hm];  // 64 MB: layer-0 hidden sequence
__device__ float g_h[2 * Bm * Hm];              // double-buffered hidden state
__device__ float g_c[Bm * Hm];                  // cell state

__device__ __forceinline__ float sigf(float x) { return 1.0f / (1.0f + expf(-x)); }

// ---------------------------------------------------------------------------
// C[M,N] = A[M,K] @ Bw[N,K]^T + b1[N] + b2[N]
// M % 128 == 0, N % 128 == 0, K % 8 == 0. 256 threads, 128x128x8 tiles, 8x8 microtile.
// ---------------------------------------------------------------------------
__global__ __launch_bounds__(256) void gemm_nt_bias(
    const float* __restrict__ A, const float* __restrict__ Bw,
    const float* __restrict__ b1, const float* __restrict__ b2,
    float* __restrict__ Cm, int M, int N, int K)
{
    __shared__ float As[8][128];
    __shared__ float Bs[8][128];
    const int bm = blockIdx.y * 128;
    const int bn = blockIdx.x * 128;
    const int tid = threadIdx.x;
    const int lr = tid >> 1;          // 0..127
    const int lk = (tid & 1) * 4;     // 0 or 4
    const int tm = (tid >> 4) * 8;    // 0..120
    const int tn = (tid & 15) * 8;    // 0..120

    float acc[8][8];
#pragma unroll
    for (int i = 0; i < 8; i++)
#pragma unroll
        for (int j = 0; j < 8; j++) acc[i][j] = 0.0f;

    const float* Ap = A + (size_t)(bm + lr) * K + lk;
    const float* Bp = Bw + (size_t)(bn + lr) * K + lk;

    for (int k0 = 0; k0 < K; k0 += 8) {
        float4 av = *(const float4*)(Ap + k0);
        float4 bv = *(const float4*)(Bp + k0);
        __syncthreads();
        As[lk + 0][lr] = av.x; As[lk + 1][lr] = av.y;
        As[lk + 2][lr] = av.z; As[lk + 3][lr] = av.w;
        Bs[lk + 0][lr] = bv.x; Bs[lk + 1][lr] = bv.y;
        Bs[lk + 2][lr] = bv.z; Bs[lk + 3][lr] = bv.w;
        __syncthreads();
#pragma unroll
        for (int kk = 0; kk < 8; kk++) {
            float ra[8], rb[8];
            *(float4*)(ra)     = *(const float4*)&As[kk][tm];
            *(float4*)(ra + 4) = *(const float4*)&As[kk][tm + 4];
            *(float4*)(rb)     = *(const float4*)&Bs[kk][tn];
            *(float4*)(rb + 4) = *(const float4*)&Bs[kk][tn + 4];
#pragma unroll
            for (int i = 0; i < 8; i++)
#pragma unroll
                for (int j = 0; j < 8; j++)
                    acc[i][j] = fmaf(ra[i], rb[j], acc[i][j]);
        }
    }

#pragma unroll
    for (int j = 0; j < 8; j++) {
        const int n = bn + tn + j;
        const float bb = b1[n] + b2[n];
#pragma unroll
        for (int i = 0; i < 8; i++) {
            Cm[(size_t)(bm + tm + i) * N + n] = acc[i][j] + bb;
        }
    }
}

// ---------------------------------------------------------------------------
// One LSTM timestep, fused: gates = xg[:,t,:] + h_in @ Whh^T for this CTA's
// 8 hidden units (32 gate columns), then sigmoid/tanh cell update.
// Grid: 128 CTAs (8 hidden units each). 128 threads. K = 1024 in chunks of 16.
// ---------------------------------------------------------------------------
__global__ __launch_bounds__(128) void lstm_step(
    const float* __restrict__ xg,    // [B*T, 4H]
    const float* __restrict__ Whh,   // [4H, H]
    const float* __restrict__ h_in,  // [B, H]
    float* __restrict__ h_out,       // [B, H]
    float* __restrict__ cst,         // [B, H]
    float* __restrict__ hseq,        // [B*T, H] or nullptr
    int t)
{
    __shared__ float Hs[16][64];
    __shared__ float Ws[16][32];
    __shared__ float Gs[64][36];     // padded: 32 gate cols per CTA

    const int h0 = blockIdx.x * 8;
    const int tid = threadIdx.x;

    // load maps
    const int hb = tid >> 1;              // 0..63 batch row
    const int hk = (tid & 1) * 8;         // 0 or 8 (two float4 loads)
    const int wn = tid >> 2;              // 0..31 gate-col within tile
    const int wk = (tid & 3) * 4;         // 0,4,8,12
    const int wrow = (wn >> 3) * Hm + h0 + (wn & 7);   // global W_hh row

    // compute map: 4 rows x 4 cols per thread
    const int tm = (tid >> 3) * 4;        // 0..60 (batch)
    const int tn = (tid & 7) * 4;         // 0..28 (gate col)

    float acc[4][4];
#pragma unroll
    for (int i = 0; i < 4; i++)
#pragma unroll
        for (int j = 0; j < 4; j++) acc[i][j] = 0.0f;

    for (int k0 = 0; k0 < Hm; k0 += 16) {
        float4 a0 = *(const float4*)&h_in[hb * Hm + k0 + hk];
        float4 a1 = *(const float4*)&h_in[hb * Hm + k0 + hk + 4];
        float4 wv = *(const float4*)&Whh[(size_t)wrow * Hm + k0 + wk];
        __syncthreads();
        Hs[hk + 0][hb] = a0.x; Hs[hk + 1][hb] = a0.y;
        Hs[hk + 2][hb] = a0.z; Hs[hk + 3][hb] = a0.w;
        Hs[hk + 4][hb] = a1.x; Hs[hk + 5][hb] = a1.y;
        Hs[hk + 6][hb] = a1.z; Hs[hk + 7][hb] = a1.w;
        Ws[wk + 0][wn] = wv.x; Ws[wk + 1][wn] = wv.y;
        Ws[wk + 2][wn] = wv.z; Ws[wk + 3][wn] = wv.w;
        __syncthreads();
#pragma unroll
        for (int kk = 0; kk < 16; kk++) {
            float ra[4], rb[4];
            *(float4*)ra = *(const float4*)&Hs[kk][tm];
            *(float4*)rb = *(const float4*)&Ws[kk][tn];
#pragma unroll
            for (int i = 0; i < 4; i++)
#pragma unroll
                for (int j = 0; j < 4; j++)
                    acc[i][j] = fmaf(ra[i], rb[j], acc[i][j]);
        }
    }

    // add precomputed input gates, stage in smem
#pragma unroll
    for (int j = 0; j < 4; j++) {
        const int n = tn + j;
        const int gcol = (n >> 3) * Hm + h0 + (n & 7);
#pragma unroll
        for (int i = 0; i < 4; i++) {
            const int b = tm + i;
            Gs[b][n] = acc[i][j] + xg[((size_t)b * Tm + t) * G4 + gcol];
        }
    }
    __syncthreads();

    // cell update: 64 batch x 8 hidden = 512 cells, 4 per thread
#pragma unroll
    for (int r = 0; r < 4; r++) {
        const int idx = tid + r * 128;
        const int b = idx >> 3;
        const int j = idx & 7;
        const float iv = sigf(Gs[b][j]);
        const float fv = sigf(Gs[b][8 + j]);
        const float gv = tanhf(Gs[b][16 + j]);
        const float ov = sigf(Gs[b][24 + j]);
        const int ci = b * Hm + h0 + j;
        const float cv = fv * cst[ci] + iv * gv;
        cst[ci] = cv;
        const float hv = ov * tanhf(cv);
        h_out[ci] = hv;
        if (hseq) hseq[((size_t)b * Tm + t) * Hm + h0 + j] = hv;
    }
}

// ---------------------------------------------------------------------------
// out[64,1000] = h_final[64,1024] @ fc_w[1000,1024]^T + fc_b
// Grid: 16 CTAs over N (64 cols each), 256 threads, 4x4 microtile.
// ---------------------------------------------------------------------------
__global__ __launch_bounds__(256) void fc_kernel(
    const float* __restrict__ hfin, const float* __restrict__ Wf,
    const float* __restrict__ bf, float* __restrict__ out)
{
    __shared__ float Hs[16][64];
    __shared__ float Ws[16][64];
    const int n0 = blockIdx.x * 64;
    const int tid = threadIdx.x;
    const int lb = tid >> 2;           // 0..63
    const int lk = (tid & 3) * 4;      // 0,4,8,12
    const int tm = (tid >> 4) * 4;     // 0..60 (batch)
    const int tn = (tid & 15) * 4;     // 0..60 (class)

    float acc[4][4];
#pragma unroll
    for (int i = 0; i < 4; i++)
#pragma unroll
        for (int j = 0; j < 4; j++) acc[i][j] = 0.0f;

    for (int k0 = 0; k0 < Hm; k0 += 16) {
        float4 hv = *(const float4*)&hfin[lb * Hm + k0 + lk];
        const int n = n0 + lb;
        float4 wv = make_float4(0.f, 0.f, 0.f, 0.f);
        if (n < C_OUT) wv = *(const float4*)&Wf[(size_t)n * Hm + k0 + lk];
        __syncthreads();
        Hs[lk + 0][lb] = hv.x; Hs[lk + 1][lb] = hv.y;
        Hs[lk + 2][lb] = hv.z; Hs[lk + 3][lb] = hv.w;
        Ws[lk + 0][lb] = wv.x; Ws[lk + 1][lb] = wv.y;
        Ws[lk + 2][lb] = wv.z; Ws[lk + 3][lb] = wv.w;
        __syncthreads();
#pragma unroll
        for (int kk = 0; kk < 16; kk++) {
            float ra[4], rb[4];
            *(float4*)ra = *(const float4*)&Hs[kk][tm];
            *(float4*)rb = *(const float4*)&Ws[kk][tn];
#pragma unroll
            for (int i = 0; i < 4; i++)
#pragma unroll
                for (int j = 0; j < 4; j++)
                    acc[i][j] = fmaf(ra[i], rb[j], acc[i][j]);
        }
    }

#pragma unroll
    for (int j = 0; j < 4; j++) {
        const int n = n0 + tn + j;
        if (n < C_OUT) {
            const float bb = bf[n];
#pragma unroll
            for (int i = 0; i < 4; i++)
                out[(tm + i) * C_OUT + n] = acc[i][j] + bb;
        }
    }
}

// ---------------------------------------------------------------------------
extern "C" void kernel_launch(void* const* d_in, const int* in_sizes, int n_in,
                              void* d_out, int out_size)
{
    const float* x     = (const float*)d_in[0];
    const float* W_ih0 = (const float*)d_in[1];
    const float* W_hh0 = (const float*)d_in[2];
    const float* b_ih0 = (const float*)d_in[3];
    const float* b_hh0 = (const float*)d_in[4];
    const float* W_ih1 = (const float*)d_in[5];
    const float* W_hh1 = (const float*)d_in[6];
    const float* b_ih1 = (const float*)d_in[7];
    const float* b_hh1 = (const float*)d_in[8];
    const float* fc_w  = (const float*)d_in[9];
    const float* fc_b  = (const float*)d_in[10];
    float* out = (float*)d_out;

    float *xg, *hseq, *h, *c;
    cudaGetSymbolAddress((void**)&xg, g_xg);
    cudaGetSymbolAddress((void**)&hseq, g_hseq);
    cudaGetSymbolAddress((void**)&h, g_h);
    cudaGetSymbolAddress((void**)&c, g_c);

    const dim3 gridA(G4 / 128, (Bm * Tm) / 128);

    // ---- layer 0 ----
    cudaMemsetAsync(h, 0, 2 * Bm * Hm * sizeof(float));
    cudaMemsetAsync(c, 0, Bm * Hm * sizeof(float));
    gemm_nt_bias<<<gridA, 256>>>(x, W_ih0, b_ih0, b_hh0, xg, Bm * Tm, G4, DIN);
    for (int t = 0; t < Tm; t++) {
        lstm_step<<<128, 128>>>(xg, W_hh0,
                                h + (t & 1) * Bm * Hm,
                                h + ((t + 1) & 1) * Bm * Hm,
                                c, hseq, t);
    }

    // ---- layer 1 ----
    gemm_nt_bias<<<gridA, 256>>>(hseq, W_ih1, b_ih1, b_hh1, xg, Bm * Tm, G4, Hm);
    cudaMemsetAsync(h, 0, 2 * Bm * Hm * sizeof(float));
    cudaMemsetAsync(c, 0, Bm * Hm * sizeof(float));
    for (int t = 0; t < Tm; t++) {
        lstm_step<<<128, 128>>>(xg, W_hh1,
                                h + (t & 1) * Bm * Hm,
                                h + ((t + 1) & 1) * Bm * Hm,
                                c, nullptr, t);
    }

    // ---- classifier on final hidden state (T even -> buffer 0) ----
    fc_kernel<<<16, 256>>>(h, fc_w, fc_b, out);
}

// round 2
// speedup vs baseline: 2.0419x; 2.0419x over previous
#include <cuda_runtime.h>
#include <cuda_bf16.h>
#include <stdint.h>
#include <math.h>

#define Bm 64
#define Tm 256
#define DIN 512
#define Hm 1024
#define G4 4096
#define C_OUT 1000
#define BT (Bm*Tm)

// ---------------- device scratch (packed bf16 pairs: 2 elems / uint32) ------
__device__ uint32_t g_xh[BT*DIN/2],  g_xl[BT*DIN/2];            // x split
__device__ uint32_t g_sh[(size_t)BT*Hm/2], g_sl[(size_t)BT*Hm/2]; // hseq split
__device__ uint32_t g_wih0h[G4*DIN/2], g_wih0l[G4*DIN/2];
__device__ uint32_t g_whh0h[G4*Hm/2],  g_whh0l[G4*Hm/2];
__device__ uint32_t g_wih1h[G4*Hm/2],  g_wih1l[G4*Hm/2];
__device__ uint32_t g_whh1h[G4*Hm/2],  g_whh1l[G4*Hm/2];
__device__ uint32_t g_fwh[C_OUT*Hm/2], g_fwl[C_OUT*Hm/2];
__device__ uint32_t g_hh[2][Bm*Hm/2],  g_hl[2][Bm*Hm/2];        // recurrent h split
__device__ float    g_c[Bm*Hm];
__device__ float    g_xg[(size_t)BT*G4];                        // fp32 input-gate precompute

// ---------------- helpers ----------------------------------------------------
__device__ __forceinline__ float sigf(float x) { return 1.0f / (1.0f + __expf(-x)); }
__device__ __forceinline__ float tanhx(float x) {
    float a = fabsf(x);
    float e = __expf(-2.0f * a);
    float r = (1.0f - e) / (1.0f + e);
    return x < 0.0f ? -r : r;
}

__device__ __forceinline__ void mma_bf16(float* c,
    uint32_t a0, uint32_t a1, uint32_t a2, uint32_t a3, uint32_t b0, uint32_t b1)
{
    asm volatile(
        "mma.sync.aligned.m16n8k16.row.col.f32.bf16.bf16.f32 "
        "{%0,%1,%2,%3}, {%4,%5,%6,%7}, {%8,%9}, {%0,%1,%2,%3};\n"
        : "+f"(c[0]), "+f"(c[1]), "+f"(c[2]), "+f"(c[3])
        : "r"(a0), "r"(a1), "r"(a2), "r"(a3), "r"(b0), "r"(b1));
}

// ---------------- split fp32 -> bf16 hi/lo (packed pairs) --------------------
__global__ void split2(const float* __restrict__ src,
                       uint32_t* __restrict__ hi, uint32_t* __restrict__ lo, int n2)
{
    int i = blockIdx.x * blockDim.x + threadIdx.x;
    if (i >= n2) return;
    float2 v = ((const float2*)src)[i];
    __nv_bfloat16 h0 = __float2bfloat16_rn(v.x);
    __nv_bfloat16 h1 = __float2bfloat16_rn(v.y);
    float l0f = v.x - __bfloat162float(h0);
    float l1f = v.y - __bfloat162float(h1);
    __nv_bfloat16 l0 = __float2bfloat16_rn(l0f);
    __nv_bfloat16 l1 = __float2bfloat16_rn(l1f);
    hi[i] = (uint32_t)__bfloat16_as_ushort(h0) | ((uint32_t)__bfloat16_as_ushort(h1) << 16);
    lo[i] = (uint32_t)__bfloat16_as_ushort(l0) | ((uint32_t)__bfloat16_as_ushort(l1) << 16);
}

// ---------------- generic bf16x3 GEMM: C[M,N] = A[M,K] @ B[N,K]^T + b1 + b2 --
// CTA 256 thr = 8 warps (4m x 2n), CTA tile 128x128, warp tile 32x64.
// Fragments loaded directly from global (L2-resident operands). K % 16 == 0.
__global__ __launch_bounds__(256, 1) void gemm3(
    const uint32_t* __restrict__ Ah, const uint32_t* __restrict__ Al,
    const uint32_t* __restrict__ Bh, const uint32_t* __restrict__ Bl,
    const float* __restrict__ b1, const float* __restrict__ b2,
    float* __restrict__ C, int M, int N, int K)
{
    const int K2 = K >> 1;
    const int tid = threadIdx.x;
    const int wid = tid >> 5, lane = tid & 31;
    const int g = lane >> 2, tig = lane & 3;
    const int wm = wid >> 1, wn = wid & 1;
    const int m0 = blockIdx.y * 128 + wm * 32;
    const int n0 = blockIdx.x * 128 + wn * 64;

    int aoff[2][2];
#pragma unroll
    for (int im = 0; im < 2; im++) {
        int r0 = m0 + 16 * im + g;
        int r1 = r0 + 8;
        aoff[im][0] = min(r0, M - 1) * K2;
        aoff[im][1] = min(r1, M - 1) * K2;
    }
    int boff[8];
#pragma unroll
    for (int in = 0; in < 8; in++) {
        int r = n0 + 8 * in + g;
        boff[in] = (r < N ? r : 0) * K2;
    }

    float acc[2][8][4];
#pragma unroll
    for (int im = 0; im < 2; im++)
#pragma unroll
        for (int in = 0; in < 8; in++)
#pragma unroll
            for (int q = 0; q < 4; q++) acc[im][in][q] = 0.0f;

    for (int kw = 0; kw < K2; kw += 8) {   // 16 elements of K per iter
        uint32_t ah[2][4], al[2][4];
#pragma unroll
        for (int im = 0; im < 2; im++) {
            ah[im][0] = Ah[aoff[im][0] + kw + tig];
            ah[im][1] = Ah[aoff[im][1] + kw + tig];
            ah[im][2] = Ah[aoff[im][0] + kw + 4 + tig];
            ah[im][3] = Ah[aoff[im][1] + kw + 4 + tig];
            al[im][0] = Al[aoff[im][0] + kw + tig];
            al[im][1] = Al[aoff[im][1] + kw + tig];
            al[im][2] = Al[aoff[im][0] + kw + 4 + tig];
            al[im][3] = Al[aoff[im][1] + kw + 4 + tig];
        }
#pragma unroll
        for (int in = 0; in < 8; in++) {
            uint32_t bh0 = Bh[boff[in] + kw + tig];
            uint32_t bh1 = Bh[boff[in] + kw + 4 + tig];
            uint32_t bl0 = Bl[boff[in] + kw + tig];
            uint32_t bl1 = Bl[boff[in] + kw + 4 + tig];
#pragma unroll
            for (int im = 0; im < 2; im++) {
                mma_bf16(acc[im][in], ah[im][0], ah[im][1], ah[im][2], ah[im][3], bh0, bh1);
                mma_bf16(acc[im][in], ah[im][0], ah[im][1], ah[im][2], ah[im][3], bl0, bl1);
                mma_bf16(acc[im][in], al[im][0], al[im][1], al[im][2], al[im][3], bh0, bh1);
            }
        }
    }

#pragma unroll
    for (int im = 0; im < 2; im++) {
        const int r0 = m0 + 16 * im + g;
        const int r1 = r0 + 8;
#pragma unroll
        for (int in = 0; in < 8; in++) {
            const int c = n0 + 8 * in + 2 * tig;
            if (c < N) {
                float bb0 = b1[c]     + (b2 ? b2[c]     : 0.0f);
                float bb1 = b1[c + 1] + (b2 ? b2[c + 1] : 0.0f);
                if (r0 < M) {
                    float2 v = make_float2(acc[im][in][0] + bb0, acc[im][in][1] + bb1);
                    *(float2*)&C[(size_t)r0 * N + c] = v;
                }
                if (r1 < M) {
                    float2 v = make_float2(acc[im][in][2] + bb0, acc[im][in][3] + bb1);
                    *(float2*)&C[(size_t)r1 * N + c] = v;
                }
            }
        }
    }
}

// ---------------- fused LSTM step, bf16x3 tensor-core ------------------------
// gates[64, 4096] = h[64,1024] @ Whh^T + xg[:,t,:]; CTA owns 8 hidden units
// (32 gate cols). 8 warps split K 8-ways, full 64x32 tile each; 2-stage smem
// reduction, then fused activations + cell update; writes h split (+ hseq split).
__global__ __launch_bounds__(256, 1) void step3(
    const uint32_t* __restrict__ Wh, const uint32_t* __restrict__ Wl,
    const uint32_t* __restrict__ hinH, const uint32_t* __restrict__ hinL,
    uint32_t* __restrict__ houtH, uint32_t* __restrict__ houtL,
    float* __restrict__ cst, const float* __restrict__ xg,
    uint32_t* __restrict__ seqH, uint32_t* __restrict__ seqL, int t)
{
    __shared__ float red[4][64][40];
    const int tid = threadIdx.x;
    const int wid = tid >> 5, lane = tid & 31;
    const int g = lane >> 2, tig = lane & 3;
    const int h0 = blockIdx.x * 8;
    const int K2 = Hm / 2;            // 512 uints per row
    const int kbase = wid * 64;       // this warp's K slice: 128 elems = 64 uints

    int aoff[4][2];
#pragma unroll
    for (int im = 0; im < 4; im++) {
        aoff[im][0] = (16 * im + g) * K2;
        aoff[im][1] = (16 * im + g + 8) * K2;
    }
    int boff[4];
#pragma unroll
    for (int in = 0; in < 4; in++)
        boff[in] = (in * Hm + h0 + g) * K2;   // gate rows: in*1024 + h0 + g

    float acc[4][4][4];
#pragma unroll
    for (int im = 0; im < 4; im++)
#pragma unroll
        for (int in = 0; in < 4; in++)
#pragma unroll
            for (int q = 0; q < 4; q++) acc[im][in][q] = 0.0f;

#pragma unroll
    for (int kk = 0; kk < 8; kk++) {
        const int kw = kbase + kk * 8;
        uint32_t ah[4][4], al[4][4];
#pragma unroll
        for (int im = 0; im < 4; im++) {
            ah[im][0] = hinH[aoff[im][0] + kw + tig];
            ah[im][1] = hinH[aoff[im][1] + kw + tig];
            ah[im][2] = hinH[aoff[im][0] + kw + 4 + tig];
            ah[im][3] = hinH[aoff[im][1] + kw + 4 + tig];
            al[im][0] = hinL[aoff[im][0] + kw + tig];
            al[im][1] = hinL[aoff[im][1] + kw + tig];
            al[im][2] = hinL[aoff[im][0] + kw + 4 + tig];
            al[im][3] = hinL[aoff[im][1] + kw + 4 + tig];
        }
#pragma unroll
        for (int in = 0; in < 4; in++) {
            uint32_t bh0 = Wh[boff[in] + kw + tig];
            uint32_t bh1 = Wh[boff[in] + kw + 4 + tig];
            uint32_t bl0 = Wl[boff[in] + kw + tig];
            uint32_t bl1 = Wl[boff[in] + kw + 4 + tig];
#pragma unroll
            for (int im = 0; im < 4; im++) {
                mma_bf16(acc[im][in], ah[im][0], ah[im][1], ah[im][2], ah[im][3], bh0, bh1);
                mma_bf16(acc[im][in], ah[im][0], ah[im][1], ah[im][2], ah[im][3], bl0, bl1);
                mma_bf16(acc[im][in], al[im][0], al[im][1], al[im][2], al[im][3], bh0, bh1);
            }
        }
    }

    // ---- cross-warp K reduction (8 -> 4 -> smem) ----
    if (wid >= 4) {
        const int p = wid - 4;
#pragma unroll
        for (int im = 0; im < 4; im++)
#pragma unroll
            for (int in = 0; in < 4; in++) {
                *(float2*)&red[p][16 * im + g][8 * in + 2 * tig] =
                    make_float2(acc[im][in][0], acc[im][in][1]);
                *(float2*)&red[p][16 * im + g + 8][8 * in + 2 * tig] =
                    make_float2(acc[im][in][2], acc[im][in][3]);
            }
    }
    __syncthreads();
    if (wid < 4) {
        const int p = wid;
#pragma unroll
        for (int im = 0; im < 4; im++)
#pragma unroll
            for (int in = 0; in < 4; in++) {
                float2 v0 = *(float2*)&red[p][16 * im + g][8 * in + 2 * tig];
                float2 v1 = *(float2*)&red[p][16 * im + g + 8][8 * in + 2 * tig];
                *(float2*)&red[p][16 * im + g][8 * in + 2 * tig] =
                    make_float2(acc[im][in][0] + v0.x, acc[im][in][1] + v0.y);
                *(float2*)&red[p][16 * im + g + 8][8 * in + 2 * tig] =
                    make_float2(acc[im][in][2] + v1.x, acc[im][in][3] + v1.y);
            }
    }
    __syncthreads();

    // ---- epilogue: 256 threads, each handles (b, jj) and (b, jj+1) ----
    const int b  = tid >> 2;          // 0..63
    const int jj = (tid & 3) * 2;     // 0,2,4,6
    float gate[4][2];
#pragma unroll
    for (int gt = 0; gt < 4; gt++) {
        float sx = 0.0f, sy = 0.0f;
#pragma unroll
        for (int p = 0; p < 4; p++) {
            float2 v = *(float2*)&red[p][b][8 * gt + jj];
            sx += v.x; sy += v.y;
        }
        const float2 xv = *(const float2*)&xg[(size_t)(b * Tm + t) * G4 + gt * Hm + h0 + jj];
        gate[gt][0] = sx + xv.x;
        gate[gt][1] = sy + xv.y;
    }

    const int ci = b * Hm + h0 + jj;
    float2 cv = *(float2*)&cst[ci];
    float hv[2];
#pragma unroll
    for (int e = 0; e < 2; e++) {
        float iv = sigf(gate[0][e]);
        float fv = sigf(gate[1][e]);
        float gv = tanhx(gate[2][e]);
        float ov = sigf(gate[3][e]);
        float cc = (e == 0 ? cv.x : cv.y);
        float cn = fv * cc + iv * gv;
        if (e == 0) cv.x = cn; else cv.y = cn;
        hv[e] = ov * tanhx(cn);
    }
    *(float2*)&cst[ci] = cv;

    __nv_bfloat16 b0 = __float2bfloat16_rn(hv[0]);
    __nv_bfloat16 b1 = __float2bfloat16_rn(hv[1]);
    float l0f = hv[0] - __bfloat162float(b0);
    float l1f = hv[1] - __bfloat162float(b1);
    __nv_bfloat16 l0 = __float2bfloat16_rn(l0f);
    __nv_bfloat16 l1 = __float2bfloat16_rn(l1f);
    uint32_t uhi = (uint32_t)__bfloat16_as_ushort(b0) | ((uint32_t)__bfloat16_as_ushort(b1) << 16);
    uint32_t ulo = (uint32_t)__bfloat16_as_ushort(l0) | ((uint32_t)__bfloat16_as_ushort(l1) << 16);
    const int hidx = ci >> 1;
    houtH[hidx] = uhi;
    houtL[hidx] = ulo;
    if (seqH) {
        const int si = ((b * Tm + t) * Hm + h0 + jj) >> 1;
        seqH[si] = uhi;
        seqL[si] = ulo;
    }
}

// ---------------------------------------------------------------------------
extern "C" void kernel_launch(void* const* d_in, const int* in_sizes, int n_in,
                              void* d_out, int out_size)
{
    const float* x     = (const float*)d_in[0];
    const float* W_ih0 = (const float*)d_in[1];
    const float* W_hh0 = (const float*)d_in[2];
    const float* b_ih0 = (const float*)d_in[3];
    const float* b_hh0 = (const float*)d_in[4];
    const float* W_ih1 = (const float*)d_in[5];
    const float* W_hh1 = (const float*)d_in[6];
    const float* b_ih1 = (const float*)d_in[7];
    const float* b_hh1 = (const float*)d_in[8];
    const float* fc_w  = (const float*)d_in[9];
    const float* fc_b  = (const float*)d_in[10];
    float* out = (float*)d_out;

    uint32_t *xh, *xl, *sh, *sl, *wih0h, *wih0l, *whh0h, *whh0l;
    uint32_t *wih1h, *wih1l, *whh1h, *whh1l, *fwh, *fwl, *hh, *hl;
    float *cst, *xg;
    cudaGetSymbolAddress((void**)&xh, g_xh);       cudaGetSymbolAddress((void**)&xl, g_xl);
    cudaGetSymbolAddress((void**)&sh, g_sh);       cudaGetSymbolAddress((void**)&sl, g_sl);
    cudaGetSymbolAddress((void**)&wih0h, g_wih0h); cudaGetSymbolAddress((void**)&wih0l, g_wih0l);
    cudaGetSymbolAddress((void**)&whh0h, g_whh0h); cudaGetSymbolAddress((void**)&whh0l, g_whh0l);
    cudaGetSymbolAddress((void**)&wih1h, g_wih1h); cudaGetSymbolAddress((void**)&wih1l, g_wih1l);
    cudaGetSymbolAddress((void**)&whh1h, g_whh1h); cudaGetSymbolAddress((void**)&whh1l, g_whh1l);
    cudaGetSymbolAddress((void**)&fwh, g_fwh);     cudaGetSymbolAddress((void**)&fwl, g_fwl);
    cudaGetSymbolAddress((void**)&hh, g_hh);       cudaGetSymbolAddress((void**)&hl, g_hl);
    cudaGetSymbolAddress((void**)&cst, g_c);       cudaGetSymbolAddress((void**)&xg, g_xg);

    const int HBUF = Bm * Hm / 2;  // uints per h buffer

    // ---- split all operands into bf16 hi/lo ----
    auto splits = [&](const float* s, uint32_t* h, uint32_t* l, int elems) {
        int n2 = elems / 2;
        split2<<<(n2 + 255) / 256, 256>>>(s, h, l, n2);
    };
    splits(x,     xh,    xl,    BT * DIN);
    splits(W_ih0, wih0h, wih0l, G4 * DIN);
    splits(W_hh0, whh0h, whh0l, G4 * Hm);
    splits(W_ih1, wih1h, wih1l, G4 * Hm);
    splits(W_hh1, whh1h, whh1l, G4 * Hm);
    splits(fc_w,  fwh,   fwl,   C_OUT * Hm);

    // ---- layer 0 ----
    cudaMemsetAsync(hh, 0, HBUF * 4);
    cudaMemsetAsync(hl, 0, HBUF * 4);
    cudaMemsetAsync(cst, 0, Bm * Hm * sizeof(float));
    gemm3<<<dim3(G4 / 128, BT / 128), 256>>>(xh, xl, wih0h, wih0l,
                                             b_ih0, b_hh0, xg, BT, G4, DIN);
    for (int t = 0; t < Tm; t++) {
        step3<<<128, 256>>>(whh0h, whh0l,
                            hh + (t & 1) * HBUF, hl + (t & 1) * HBUF,
                            hh + ((t + 1) & 1) * HBUF, hl + ((t + 1) & 1) * HBUF,
                            cst, xg, sh, sl, t);
    }

    // ---- layer 1 ----
    gemm3<<<dim3(G4 / 128, BT / 128), 256>>>(sh, sl, wih1h, wih1l,
                                             b_ih1, b_hh1, xg, BT, G4, Hm);
    cudaMemsetAsync(hh, 0, HBUF * 4);
    cudaMemsetAsync(hl, 0, HBUF * 4);
    cudaMemsetAsync(cst, 0, Bm * Hm * sizeof(float));
    for (int t = 0; t < Tm; t++) {
        step3<<<128, 256>>>(whh1h, whh1l,
                            hh + (t & 1) * HBUF, hl + (t & 1) * HBUF,
                            hh + ((t + 1) & 1) * HBUF, hl + ((t + 1) & 1) * HBUF,
                            cst, xg, (uint32_t*)nullptr, (uint32_t*)nullptr, t);
    }

    // ---- classifier on final hidden state (T even -> buffer 0) ----
    gemm3<<<dim3((C_OUT + 127) / 128, 1), 256>>>(hh, hl, fwh, fwl,
                                                 fc_b, (const float*)nullptr,
                                                 out, Bm, C_OUT, Hm);
}

// round 3
// speedup vs baseline: 3.2941x; 1.6133x over previous
#include <cuda_runtime.h>
#include <cuda_bf16.h>
#include <stdint.h>
#include <math.h>

#define Bm 64
#define Tm 256
#define DIN 512
#define Hm 1024
#define G4 4096
#define C_OUT 1000
#define BT (Bm*Tm)

// ---------------- device scratch (packed bf16 pairs: 2 elems / uint32) ------
__device__ uint32_t g_xh[BT*DIN/2],  g_xl[BT*DIN/2];
__device__ uint32_t g_sh[(size_t)BT*Hm/2], g_sl[(size_t)BT*Hm/2];
__device__ uint32_t g_wih0h[G4*DIN/2], g_wih0l[G4*DIN/2];
__device__ uint32_t g_whh0h[G4*Hm/2],  g_whh0l[G4*Hm/2];
__device__ uint32_t g_wih1h[G4*Hm/2],  g_wih1l[G4*Hm/2];
__device__ uint32_t g_whh1h[G4*Hm/2],  g_whh1l[G4*Hm/2];
__device__ uint32_t g_fwh[C_OUT*Hm/2], g_fwl[C_OUT*Hm/2];
__device__ uint32_t g_hh[2][Bm*Hm/2],  g_hl[2][Bm*Hm/2];
__device__ float    g_c[Bm*Hm];
__device__ float    g_xg[(size_t)BT*G4];

// ---------------- helpers ----------------------------------------------------
__device__ __forceinline__ float sigf(float x) { return 1.0f / (1.0f + __expf(-x)); }
__device__ __forceinline__ float tanhx(float x) {
    float a = fabsf(x);
    float e = __expf(-2.0f * a);
    float r = (1.0f - e) / (1.0f + e);
    return x < 0.0f ? -r : r;
}
__device__ __forceinline__ uint32_t smemu32(const void* p) {
    return (uint32_t)__cvta_generic_to_shared(p);
}
__device__ __forceinline__ void ldsm4(uint32_t& r0, uint32_t& r1, uint32_t& r2, uint32_t& r3,
                                      uint32_t addr) {
    asm volatile("ldmatrix.sync.aligned.m8n8.x4.shared.b16 {%0,%1,%2,%3}, [%4];"
                 : "=r"(r0), "=r"(r1), "=r"(r2), "=r"(r3) : "r"(addr));
}
__device__ __forceinline__ void mma_bf16(float* c,
    uint32_t a0, uint32_t a1, uint32_t a2, uint32_t a3, uint32_t b0, uint32_t b1)
{
    asm volatile(
        "mma.sync.aligned.m16n8k16.row.col.f32.bf16.bf16.f32 "
        "{%0,%1,%2,%3}, {%4,%5,%6,%7}, {%8,%9}, {%0,%1,%2,%3};\n"
        : "+f"(c[0]), "+f"(c[1]), "+f"(c[2]), "+f"(c[3])
        : "r"(a0), "r"(a1), "r"(a2), "r"(a3), "r"(b0), "r"(b1));
}

// ---------------- split fp32 -> bf16 hi/lo (packed pairs) --------------------
__global__ void split2(const float* __restrict__ src,
                       uint32_t* __restrict__ hi, uint32_t* __restrict__ lo, int n2)
{
    int i = blockIdx.x * blockDim.x + threadIdx.x;
    if (i >= n2) return;
    float2 v = ((const float2*)src)[i];
    __nv_bfloat16 h0 = __float2bfloat16_rn(v.x);
    __nv_bfloat16 h1 = __float2bfloat16_rn(v.y);
    __nv_bfloat16 l0 = __float2bfloat16_rn(v.x - __bfloat162float(h0));
    __nv_bfloat16 l1 = __float2bfloat16_rn(v.y - __bfloat162float(h1));
    hi[i] = (uint32_t)__bfloat16_as_ushort(h0) | ((uint32_t)__bfloat16_as_ushort(h1) << 16);
    lo[i] = (uint32_t)__bfloat16_as_ushort(l0) | ((uint32_t)__bfloat16_as_ushort(l1) << 16);
}

// ============================================================================
// gemmT: C[M,N] = A[M,K] @ B[N,K]^T + b1 (+b2), bf16x3, smem-staged + ldmatrix.
// CTA tile 128x128, Kc=32. 8 warps = 2m x 4n, warp tile m64 x n32.
// Rows of A clamped for M<128 tiles; B rows + C writes guarded for ragged N.
// ============================================================================
__global__ __launch_bounds__(256, 1) void gemmT(
    const uint32_t* __restrict__ Ah, const uint32_t* __restrict__ Al,
    const uint32_t* __restrict__ Bh, const uint32_t* __restrict__ Bl,
    const float* __restrict__ b1, const float* __restrict__ b2,
    float* __restrict__ C, int M, int N, int K)
{
    // smem: row stride 20 uints (16 data + 4 pad) -> 5 16B-units/row, LDSM conflict-free
    __shared__ uint32_t AhS[128 * 20], AlS[128 * 20], BhS[128 * 20], BlS[128 * 20];

    const int K2 = K >> 1;
    const int tid = threadIdx.x;
    const int wid = tid >> 5, lane = tid & 31;
    const int g = lane >> 2, tig = lane & 3;
    const int wm = wid >> 2, wn = wid & 3;       // 2 x 4 warps
    const int bm = blockIdx.y * 128, bn = blockIdx.x * 128;

    // global load map: unit u (16B) : row = u>>2, c = u&3 ; thread covers u=tid*? ->
    // u0 = tid (rows 0..63), u1 = tid+256 (rows 64..127)
    const int lr0 = tid >> 2, lc = tid & 3;
    const int ar0 = min(bm + lr0, M - 1) * K2;
    const int ar1 = min(bm + lr0 + 64, M - 1) * K2;
    const int br0 = ((bn + lr0      < N) ? bn + lr0      : 0) * K2;
    const int br1 = ((bn + lr0 + 64 < N) ? bn + lr0 + 64 : 0) * K2;

    uint4 pA0, pA1, pAl0, pAl1, pB0, pB1, pBl0, pBl1;
    auto loadG = [&](int kc) {
        const int go = kc * 16 + lc * 4;
        pA0  = *(const uint4*)&Ah[ar0 + go];  pA1  = *(const uint4*)&Ah[ar1 + go];
        pAl0 = *(const uint4*)&Al[ar0 + go];  pAl1 = *(const uint4*)&Al[ar1 + go];
        pB0  = *(const uint4*)&Bh[br0 + go];  pB1  = *(const uint4*)&Bh[br1 + go];
        pBl0 = *(const uint4*)&Bl[br0 + go];  pBl1 = *(const uint4*)&Bl[br1 + go];
    };

    float acc[4][4][4];
#pragma unroll
    for (int im = 0; im < 4; im++)
#pragma unroll
        for (int p = 0; p < 4; p++)
#pragma unroll
            for (int q = 0; q < 4; q++) acc[im][p][q] = 0.0f;

    // ldmatrix source addresses
    const int lrow = lane & 15, lhalf = lane >> 4;
    const uint32_t aBase = smemu32(AhS), alBase = smemu32(AlS);
    const uint32_t bBase = smemu32(BhS), blBase = smemu32(BlS);

    const int nk = K >> 5;   // chunks of 32
    loadG(0);
    for (int kc = 0; kc < nk; kc++) {
        __syncthreads();
        {
            const int s0 = lr0 * 20 + lc * 4, s1 = (lr0 + 64) * 20 + lc * 4;
            *(uint4*)&AhS[s0] = pA0;  *(uint4*)&AhS[s1] = pA1;
            *(uint4*)&AlS[s0] = pAl0; *(uint4*)&AlS[s1] = pAl1;
            *(uint4*)&BhS[s0] = pB0;  *(uint4*)&BhS[s1] = pB1;
            *(uint4*)&BlS[s0] = pBl0; *(uint4*)&BlS[s1] = pBl1;
        }
        __syncthreads();
        if (kc + 1 < nk) loadG(kc + 1);

#pragma unroll
        for (int k16 = 0; k16 < 2; k16++) {
            const uint32_t coff = (uint32_t)((k16 * 2 + lhalf) * 16);
            uint32_t bh[2][4], bl[2][4];
#pragma unroll
            for (int p16 = 0; p16 < 2; p16++) {
                const uint32_t bro = (uint32_t)((wn * 32 + p16 * 16 + lrow) * 80);
                ldsm4(bh[p16][0], bh[p16][1], bh[p16][2], bh[p16][3], bBase + bro + coff);
                ldsm4(bl[p16][0], bl[p16][1], bl[p16][2], bl[p16][3], blBase + bro + coff);
            }
#pragma unroll
            for (int im = 0; im < 4; im++) {
                const uint32_t aro = (uint32_t)((wm * 64 + im * 16 + lrow) * 80);
                uint32_t ah0, ah1, ah2, ah3, al0, al1, al2, al3;
                ldsm4(ah0, ah1, ah2, ah3, aBase + aro + coff);
                ldsm4(al0, al1, al2, al3, alBase + aro + coff);
#pragma unroll
                for (int p16 = 0; p16 < 2; p16++) {
                    mma_bf16(acc[im][p16 * 2 + 0], ah0, ah1, ah2, ah3, bh[p16][0], bh[p16][2]);
                    mma_bf16(acc[im][p16 * 2 + 1], ah0, ah1, ah2, ah3, bh[p16][1], bh[p16][3]);
                    mma_bf16(acc[im][p16 * 2 + 0], ah0, ah1, ah2, ah3, bl[p16][0], bl[p16][2]);
                    mma_bf16(acc[im][p16 * 2 + 1], ah0, ah1, ah2, ah3, bl[p16][1], bl[p16][3]);
                    mma_bf16(acc[im][p16 * 2 + 0], al0, al1, al2, al3, bh[p16][0], bh[p16][2]);
                    mma_bf16(acc[im][p16 * 2 + 1], al0, al1, al2, al3, bh[p16][1], bh[p16][3]);
                }
            }
        }
    }

    // epilogue
#pragma unroll
    for (int im = 0; im < 4; im++) {
        const int r0 = bm + wm * 64 + im * 16 + g;
        const int r1 = r0 + 8;
#pragma unroll
        for (int p = 0; p < 4; p++) {
            const int c = bn + wn * 32 + p * 8 + 2 * tig;
            if (c < N) {
                const float bb0 = b1[c]     + (b2 ? b2[c]     : 0.0f);
                const float bb1 = b1[c + 1] + (b2 ? b2[c + 1] : 0.0f);
                if (r0 < M)
                    *(float2*)&C[(size_t)r0 * N + c] =
                        make_float2(acc[im][p][0] + bb0, acc[im][p][1] + bb1);
                if (r1 < M)
                    *(float2*)&C[(size_t)r1 * N + c] =
                        make_float2(acc[im][p][2] + bb0, acc[im][p][3] + bb1);
            }
        }
    }
}

// ============================================================================
// stepT: one LSTM timestep. gates[64,32cols] = h @ Whh^T (+xg), fused update.
// Grid 128 CTAs (8 hidden units = 32 gate cols each), 256 thr = 4m x 2n warps,
// warp tile m16 x n16, K=1024 in 16 chunks of 64. smem-staged + ldmatrix.
// ============================================================================
__global__ __launch_bounds__(256, 1) void stepT(
    const uint32_t* __restrict__ Wh, const uint32_t* __restrict__ Wl,
    const uint32_t* __restrict__ hinH, const uint32_t* __restrict__ hinL,
    uint32_t* __restrict__ houtH, uint32_t* __restrict__ houtL,
    float* __restrict__ cst, const float* __restrict__ xg,
    uint32_t* __restrict__ seqH, uint32_t* __restrict__ seqL, int t)
{
    // row stride 36 uints (32 data + 4 pad) -> 9 16B-units/row, LDSM conflict-free
    __shared__ uint32_t AhS[64 * 36], AlS[64 * 36], WhS[32 * 36], WlS[32 * 36];
    __shared__ float gs[64][34];

    const int tid = threadIdx.x;
    const int wid = tid >> 5, lane = tid & 31;
    const int g = lane >> 2, tig = lane & 3;
    const int wm = wid >> 1, wn = wid & 1;
    const int h0 = blockIdx.x * 8;
    const int K2 = Hm / 2;  // 512 uints per row

    // global load map: A units (16B): 512 per matrix; u0 = tid (rows 0..31), u1 = tid+256
    const int ar = tid >> 3, ac = tid & 7;          // row 0..31, unit col 0..7
    const int aoffG0 = ar * K2, aoffG1 = (ar + 32) * K2;
    // W units: 256 -> one per thread; local row 0..31 -> global gate row
    const int wrl = tid >> 3;
    const int wrowG = ((wrl >> 3) * Hm + h0 + (wrl & 7)) * K2;

    uint4 pA0, pA1, pAl0, pAl1, pW, pWl;
    auto loadG = [&](int kc) {
        const int go = kc * 32 + ac * 4;
        pA0  = *(const uint4*)&hinH[aoffG0 + go];
        pA1  = *(const uint4*)&hinH[aoffG1 + go];
        pAl0 = *(const uint4*)&hinL[aoffG0 + go];
        pAl1 = *(const uint4*)&hinL[aoffG1 + go];
        pW   = *(const uint4*)&Wh[wrowG + go];
        pWl  = *(const uint4*)&Wl[wrowG + go];
    };

    float acc[2][4];
#pragma unroll
    for (int p = 0; p < 2; p++)
#pragma unroll
        for (int q = 0; q < 4; q++) acc[p][q] = 0.0f;

    const int lrow = lane & 15, lhalf = lane >> 4;
    const uint32_t aBase  = smemu32(AhS) + (uint32_t)((wm * 16 + lrow) * 144);
    const uint32_t alBase = smemu32(AlS) + (uint32_t)((wm * 16 + lrow) * 144);
    const uint32_t bBase  = smemu32(WhS) + (uint32_t)((wn * 16 + lrow) * 144);
    const uint32_t blBase = smemu32(WlS) + (uint32_t)((wn * 16 + lrow) * 144);

    loadG(0);
#pragma unroll 1
    for (int kc = 0; kc < 16; kc++) {
        __syncthreads();
        {
            const int s0 = ar * 36 + ac * 4, s1 = (ar + 32) * 36 + ac * 4;
            *(uint4*)&AhS[s0] = pA0;  *(uint4*)&AhS[s1] = pA1;
            *(uint4*)&AlS[s0] = pAl0; *(uint4*)&AlS[s1] = pAl1;
            *(uint4*)&WhS[ar * 36 + ac * 4] = pW;
            *(uint4*)&WlS[ar * 36 + ac * 4] = pWl;
        }
        __syncthreads();
        if (kc + 1 < 16) loadG(kc + 1);

#pragma unroll
        for (int k16 = 0; k16 < 4; k16++) {
            const uint32_t coff = (uint32_t)((k16 * 2 + lhalf) * 16);
            uint32_t ah0, ah1, ah2, ah3, al0, al1, al2, al3;
            uint32_t bh0, bh1, bh2, bh3, bl0, bl1, bl2, bl3;
            ldsm4(ah0, ah1, ah2, ah3, aBase + coff);
            ldsm4(al0, al1, al2, al3, alBase + coff);
            ldsm4(bh0, bh1, bh2, bh3, bBase + coff);
            ldsm4(bl0, bl1, bl2, bl3, blBase + coff);
            mma_bf16(acc[0], ah0, ah1, ah2, ah3, bh0, bh2);
            mma_bf16(acc[1], ah0, ah1, ah2, ah3, bh1, bh3);
            mma_bf16(acc[0], ah0, ah1, ah2, ah3, bl0, bl2);
            mma_bf16(acc[1], ah0, ah1, ah2, ah3, bl1, bl3);
            mma_bf16(acc[0], al0, al1, al2, al3, bh0, bh2);
            mma_bf16(acc[1], al0, al1, al2, al3, bh1, bh3);
        }
    }

    // stage gate pre-activations into smem
    {
        const int r0 = wm * 16 + g, r1 = r0 + 8;
#pragma unroll
        for (int p = 0; p < 2; p++) {
            const int c = wn * 16 + p * 8 + 2 * tig;
            gs[r0][c] = acc[p][0]; gs[r0][c + 1] = acc[p][1];
            gs[r1][c] = acc[p][2]; gs[r1][c + 1] = acc[p][3];
        }
    }
    __syncthreads();

    // fused activations + cell update: thread -> (batch b, hidden pair jj)
    const int b  = tid >> 2;
    const int jj = (tid & 3) * 2;
    float gate[4][2];
#pragma unroll
    for (int gt = 0; gt < 4; gt++) {
        const float2 xv = *(const float2*)&xg[(size_t)(b * Tm + t) * G4 + gt * Hm + h0 + jj];
        gate[gt][0] = gs[b][8 * gt + jj]     + xv.x;
        gate[gt][1] = gs[b][8 * gt + jj + 1] + xv.y;
    }

    const int ci = b * Hm + h0 + jj;
    float2 cv = *(float2*)&cst[ci];
    float hv[2];
#pragma unroll
    for (int e = 0; e < 2; e++) {
        const float iv = sigf(gate[0][e]);
        const float fv = sigf(gate[1][e]);
        const float gv = tanhx(gate[2][e]);
        const float ov = sigf(gate[3][e]);
        const float cc = (e == 0 ? cv.x : cv.y);
        const float cn = fv * cc + iv * gv;
        if (e == 0) cv.x = cn; else cv.y = cn;
        hv[e] = ov * tanhx(cn);
    }
    *(float2*)&cst[ci] = cv;

    const __nv_bfloat16 b0 = __float2bfloat16_rn(hv[0]);
    const __nv_bfloat16 b1 = __float2bfloat16_rn(hv[1]);
    const __nv_bfloat16 l0 = __float2bfloat16_rn(hv[0] - __bfloat162float(b0));
    const __nv_bfloat16 l1 = __float2bfloat16_rn(hv[1] - __bfloat162float(b1));
    const uint32_t uhi = (uint32_t)__bfloat16_as_ushort(b0) | ((uint32_t)__bfloat16_as_ushort(b1) << 16);
    const uint32_t ulo = (uint32_t)__bfloat16_as_ushort(l0) | ((uint32_t)__bfloat16_as_ushort(l1) << 16);
    const int hidx = ci >> 1;
    houtH[hidx] = uhi;
    houtL[hidx] = ulo;
    if (seqH) {
        const int si = ((b * Tm + t) * Hm + h0 + jj) >> 1;
        seqH[si] = uhi;
        seqL[si] = ulo;
    }
}

// ---------------------------------------------------------------------------
extern "C" void kernel_launch(void* const* d_in, const int* in_sizes, int n_in,
                              void* d_out, int out_size)
{
    const float* x     = (const float*)d_in[0];
    const float* W_ih0 = (const float*)d_in[1];
    const float* W_hh0 = (const float*)d_in[2];
    const float* b_ih0 = (const float*)d_in[3];
    const float* b_hh0 = (const float*)d_in[4];
    const float* W_ih1 = (const float*)d_in[5];
    const float* W_hh1 = (const float*)d_in[6];
    const float* b_ih1 = (const float*)d_in[7];
    const float* b_hh1 = (const float*)d_in[8];
    const float* fc_w  = (const float*)d_in[9];
    const float* fc_b  = (const float*)d_in[10];
    float* out = (float*)d_out;

    uint32_t *xh, *xl, *sh, *sl, *wih0h, *wih0l, *whh0h, *whh0l;
    uint32_t *wih1h, *wih1l, *whh1h, *whh1l, *fwh, *fwl, *hh, *hl;
    float *cst, *xg;
    cudaGetSymbolAddress((void**)&xh, g_xh);       cudaGetSymbolAddress((void**)&xl, g_xl);
    cudaGetSymbolAddress((void**)&sh, g_sh);       cudaGetSymbolAddress((void**)&sl, g_sl);
    cudaGetSymbolAddress((void**)&wih0h, g_wih0h); cudaGetSymbolAddress((void**)&wih0l, g_wih0l);
    cudaGetSymbolAddress((void**)&whh0h, g_whh0h); cudaGetSymbolAddress((void**)&whh0l, g_whh0l);
    cudaGetSymbolAddress((void**)&wih1h, g_wih1h); cudaGetSymbolAddress((void**)&wih1l, g_wih1l);
    cudaGetSymbolAddress((void**)&whh1h, g_whh1h); cudaGetSymbolAddress((void**)&whh1l, g_whh1l);
    cudaGetSymbolAddress((void**)&fwh, g_fwh);     cudaGetSymbolAddress((void**)&fwl, g_fwl);
    cudaGetSymbolAddress((void**)&hh, g_hh);       cudaGetSymbolAddress((void**)&hl, g_hl);
    cudaGetSymbolAddress((void**)&cst, g_c);       cudaGetSymbolAddress((void**)&xg, g_xg);

    const int HBUF = Bm * Hm / 2;

    auto splits = [&](const float* s, uint32_t* h, uint32_t* l, int elems) {
        int n2 = elems / 2;
        split2<<<(n2 + 255) / 256, 256>>>(s, h, l, n2);
    };
    splits(x,     xh,    xl,    BT * DIN);
    splits(W_ih0, wih0h, wih0l, G4 * DIN);
    splits(W_hh0, whh0h, whh0l, G4 * Hm);
    splits(W_ih1, wih1h, wih1l, G4 * Hm);
    splits(W_hh1, whh1h, whh1l, G4 * Hm);
    splits(fc_w,  fwh,   fwl,   C_OUT * Hm);

    // ---- layer 0 ----
    cudaMemsetAsync(hh, 0, HBUF * 4);
    cudaMemsetAsync(hl, 0, HBUF * 4);
    cudaMemsetAsync(cst, 0, Bm * Hm * sizeof(float));
    gemmT<<<dim3(G4 / 128, BT / 128), 256>>>(xh, xl, wih0h, wih0l,
                                             b_ih0, b_hh0, xg, BT, G4, DIN);
    for (int t = 0; t < Tm; t++) {
        stepT<<<128, 256>>>(whh0h, whh0l,
                            hh + (t & 1) * HBUF, hl + (t & 1) * HBUF,
                            hh + ((t + 1) & 1) * HBUF, hl + ((t + 1) & 1) * HBUF,
                            cst, xg, sh, sl, t);
    }

    // ---- layer 1 ----
    gemmT<<<dim3(G4 / 128, BT / 128), 256>>>(sh, sl, wih1h, wih1l,
                                             b_ih1, b_hh1, xg, BT, G4, Hm);
    cudaMemsetAsync(hh, 0, HBUF * 4);
    cudaMemsetAsync(hl, 0, HBUF * 4);
    cudaMemsetAsync(cst, 0, Bm * Hm * sizeof(float));
    for (int t = 0; t < Tm; t++) {
        stepT<<<128, 256>>>(whh1h, whh1l,
                            hh + (t & 1) * HBUF, hl + (t & 1) * HBUF,
                            hh + ((t + 1) & 1) * HBUF, hl + ((t + 1) & 1) * HBUF,
                            cst, xg, (uint32_t*)nullptr, (uint32_t*)nullptr, t);
    }

    // ---- classifier on final hidden state (T even -> buffer 0) ----
    gemmT<<<dim3((C_OUT + 127) / 128, 1), 256>>>(hh, hl, fwh, fwl,
                                                 fc_b, (const float*)nullptr,
                                                 out, Bm, C_OUT, Hm);
}

// round 5
// speedup vs baseline: 3.3607x; 1.0202x over previous
#include <cuda_runtime.h>
#include <cuda_bf16.h>
#include <stdint.h>
#include <math.h>

#define Bm 64
#define Tm 256
#define DIN 512
#define Hm 1024
#define G4 4096
#define C_OUT 1000
#define BT (Bm*Tm)
#define NCTA 128

// ---------------- device scratch (packed bf16 pairs: 2 elems / uint32) ------
__device__ uint32_t g_xh[BT*DIN/2],  g_xl[BT*DIN/2];
__device__ uint32_t g_sh[(size_t)BT*Hm/2], g_sl[(size_t)BT*Hm/2];
__device__ uint32_t g_wih0h[G4*DIN/2], g_wih0l[G4*DIN/2];
__device__ uint32_t g_whh0h[G4*Hm/2],  g_whh0l[G4*Hm/2];
__device__ uint32_t g_wih1h[G4*Hm/2],  g_wih1l[G4*Hm/2];
__device__ uint32_t g_whh1h[G4*Hm/2],  g_whh1l[G4*Hm/2];
__device__ uint32_t g_fwh[C_OUT*Hm/2], g_fwl[C_OUT*Hm/2];
__device__ uint32_t g_hh[2][Bm*Hm/2],  g_hl[2][Bm*Hm/2];
__device__ float    g_xg[(size_t)BT*G4];

// grid barrier state
__device__ unsigned g_cnt = 0;
__device__ volatile unsigned g_gen = 0;

// ---------------- helpers ----------------------------------------------------
__device__ __forceinline__ float sigf(float x) { return 1.0f / (1.0f + __expf(-x)); }
__device__ __forceinline__ float tanhx(float x) {
    float a = fabsf(x);
    float e = __expf(-2.0f * a);
    float r = (1.0f - e) / (1.0f + e);
    return x < 0.0f ? -r : r;
}
__device__ __forceinline__ uint32_t smemu32(const void* p) {
    return (uint32_t)__cvta_generic_to_shared(p);
}
__device__ __forceinline__ void ldsm4(uint32_t& r0, uint32_t& r1, uint32_t& r2, uint32_t& r3,
                                      uint32_t addr) {
    asm volatile("ldmatrix.sync.aligned.m8n8.x4.shared.b16 {%0,%1,%2,%3}, [%4];"
                 : "=r"(r0), "=r"(r1), "=r"(r2), "=r"(r3) : "r"(addr));
}
__device__ __forceinline__ void mma_bf16(float* c,
    uint32_t a0, uint32_t a1, uint32_t a2, uint32_t a3, uint32_t b0, uint32_t b1)
{
    asm volatile(
        "mma.sync.aligned.m16n8k16.row.col.f32.bf16.bf16.f32 "
        "{%0,%1,%2,%3}, {%4,%5,%6,%7}, {%8,%9}, {%0,%1,%2,%3};\n"
        : "+f"(c[0]), "+f"(c[1]), "+f"(c[2]), "+f"(c[3])
        : "r"(a0), "r"(a1), "r"(a2), "r"(a3), "r"(b0), "r"(b1));
}

__device__ __forceinline__ void gridbar() {
    __syncthreads();
    if (threadIdx.x == 0) {
        __threadfence();
        unsigned g = g_gen;
        if (atomicAdd(&g_cnt, 1u) == NCTA - 1) {
            g_cnt = 0;
            __threadfence();
            g_gen = g + 1;
        } else {
            while (g_gen == g) { __nanosleep(64); }
        }
        __threadfence();
    }
    __syncthreads();
}

// ---------------- split fp32 -> bf16 hi/lo (packed pairs) --------------------
__global__ void split2(const float* __restrict__ src,
                       uint32_t* __restrict__ hi, uint32_t* __restrict__ lo, int n2)
{
    int i = blockIdx.x * blockDim.x + threadIdx.x;
    if (i >= n2) return;
    float2 v = ((const float2*)src)[i];
    __nv_bfloat16 h0 = __float2bfloat16_rn(v.x);
    __nv_bfloat16 h1 = __float2bfloat16_rn(v.y);
    __nv_bfloat16 l0 = __float2bfloat16_rn(v.x - __bfloat162float(h0));
    __nv_bfloat16 l1 = __float2bfloat16_rn(v.y - __bfloat162float(h1));
    hi[i] = (uint32_t)__bfloat16_as_ushort(h0) | ((uint32_t)__bfloat16_as_ushort(h1) << 16);
    lo[i] = (uint32_t)__bfloat16_as_ushort(l0) | ((uint32_t)__bfloat16_as_ushort(l1) << 16);
}

// ============================================================================
// gemmT: unchanged (bf16x3, smem-staged + ldmatrix).
// ============================================================================
__global__ __launch_bounds__(256, 1) void gemmT(
    const uint32_t* __restrict__ Ah, const uint32_t* __restrict__ Al,
    const uint32_t* __restrict__ Bh, const uint32_t* __restrict__ Bl,
    const float* __restrict__ b1, const float* __restrict__ b2,
    float* __restrict__ C, int M, int N, int K)
{
    __shared__ uint32_t AhS[128 * 20], AlS[128 * 20], BhS[128 * 20], BlS[128 * 20];

    const int K2 = K >> 1;
    const int tid = threadIdx.x;
    const int wid = tid >> 5, lane = tid & 31;
    const int g = lane >> 2, tig = lane & 3;
    const int wm = wid >> 2, wn = wid & 3;
    const int bm = blockIdx.y * 128, bn = blockIdx.x * 128;

    const int lr0 = tid >> 2, lc = tid & 3;
    const int ar0 = min(bm + lr0, M - 1) * K2;
    const int ar1 = min(bm + lr0 + 64, M - 1) * K2;
    const int br0 = ((bn + lr0      < N) ? bn + lr0      : 0) * K2;
    const int br1 = ((bn + lr0 + 64 < N) ? bn + lr0 + 64 : 0) * K2;

    uint4 pA0, pA1, pAl0, pAl1, pB0, pB1, pBl0, pBl1;
    auto loadG = [&](int kc) {
        const int go = kc * 16 + lc * 4;
        pA0  = *(const uint4*)&Ah[ar0 + go];  pA1  = *(const uint4*)&Ah[ar1 + go];
        pAl0 = *(const uint4*)&Al[ar0 + go];  pAl1 = *(const uint4*)&Al[ar1 + go];
        pB0  = *(const uint4*)&Bh[br0 + go];  pB1  = *(const uint4*)&Bh[br1 + go];
        pBl0 = *(const uint4*)&Bl[br0 + go];  pBl1 = *(const uint4*)&Bl[br1 + go];
    };

    float acc[4][4][4];
#pragma unroll
    for (int im = 0; im < 4; im++)
#pragma unroll
        for (int p = 0; p < 4; p++)
#pragma unroll
            for (int q = 0; q < 4; q++) acc[im][p][q] = 0.0f;

    const int lrow = lane & 15, lhalf = lane >> 4;
    const uint32_t aBase = smemu32(AhS), alBase = smemu32(AlS);
    const uint32_t bBase = smemu32(BhS), blBase = smemu32(BlS);

    const int nk = K >> 5;
    loadG(0);
    for (int kc = 0; kc < nk; kc++) {
        __syncthreads();
        {
            const int s0 = lr0 * 20 + lc * 4, s1 = (lr0 + 64) * 20 + lc * 4;
            *(uint4*)&AhS[s0] = pA0;  *(uint4*)&AhS[s1] = pA1;
            *(uint4*)&AlS[s0] = pAl0; *(uint4*)&AlS[s1] = pAl1;
            *(uint4*)&BhS[s0] = pB0;  *(uint4*)&BhS[s1] = pB1;
            *(uint4*)&BlS[s0] = pBl0; *(uint4*)&BlS[s1] = pBl1;
        }
        __syncthreads();
        if (kc + 1 < nk) loadG(kc + 1);

#pragma unroll
        for (int k16 = 0; k16 < 2; k16++) {
            const uint32_t coff = (uint32_t)((k16 * 2 + lhalf) * 16);
            uint32_t bh[2][4], bl[2][4];
#pragma unroll
            for (int p16 = 0; p16 < 2; p16++) {
                const uint32_t bro = (uint32_t)((wn * 32 + p16 * 16 + lrow) * 80);
                ldsm4(bh[p16][0], bh[p16][1], bh[p16][2], bh[p16][3], bBase + bro + coff);
                ldsm4(bl[p16][0], bl[p16][1], bl[p16][2], bl[p16][3], blBase + bro + coff);
            }
#pragma unroll
            for (int im = 0; im < 4; im++) {
                const uint32_t aro = (uint32_t)((wm * 64 + im * 16 + lrow) * 80);
                uint32_t ah0, ah1, ah2, ah3, al0, al1, al2, al3;
                ldsm4(ah0, ah1, ah2, ah3, aBase + aro + coff);
                ldsm4(al0, al1, al2, al3, alBase + aro + coff);
#pragma unroll
                for (int p16 = 0; p16 < 2; p16++) {
                    mma_bf16(acc[im][p16 * 2 + 0], ah0, ah1, ah2, ah3, bh[p16][0], bh[p16][2]);
                    mma_bf16(acc[im][p16 * 2 + 1], ah0, ah1, ah2, ah3, bh[p16][1], bh[p16][3]);
                    mma_bf16(acc[im][p16 * 2 + 0], ah0, ah1, ah2, ah3, bl[p16][0], bl[p16][2]);
                    mma_bf16(acc[im][p16 * 2 + 1], ah0, ah1, ah2, ah3, bl[p16][1], bl[p16][3]);
                    mma_bf16(acc[im][p16 * 2 + 0], al0, al1, al2, al3, bh[p16][0], bh[p16][2]);
                    mma_bf16(acc[im][p16 * 2 + 1], al0, al1, al2, al3, bh[p16][1], bh[p16][3]);
                }
            }
        }
    }

#pragma unroll
    for (int im = 0; im < 4; im++) {
        const int r0 = bm + wm * 64 + im * 16 + g;
        const int r1 = r0 + 8;
#pragma unroll
        for (int p = 0; p < 4; p++) {
            const int c = bn + wn * 32 + p * 8 + 2 * tig;
            if (c < N) {
                const float bb0 = b1[c]     + (b2 ? b2[c]     : 0.0f);
                const float bb1 = b1[c + 1] + (b2 ? b2[c + 1] : 0.0f);
                if (r0 < M)
                    *(float2*)&C[(size_t)r0 * N + c] =
                        make_float2(acc[im][p][0] + bb0, acc[im][p][1] + bb1);
                if (r1 < M)
                    *(float2*)&C[(size_t)r1 * N + c] =
                        make_float2(acc[im][p][2] + bb0, acc[im][p][3] + bb1);
            }
        }
    }
}

// ============================================================================
// lstm_persist: one launch runs ALL 256 timesteps of one layer.
// 128 CTAs x 256 thr. CTA owns 8 hidden units (32 gate rows).
// W slice (hi+lo) cached in smem once; cell state in registers; h exchanged
// via global (ldcg) with grid-wide barrier per step.
// FIX vs R4: inner k16 loop covers all 8 x 16 = 128 K-elems per chunk, and
// W column offset indexes (kc*8 + k16) to span the full K = 1024.
// ============================================================================
#define SW_OFF_WL 16512
#define SW_OFF_AH 33024
#define SW_OFF_AL 37376
#define SW_OFF_GS 41728
#define SMEM_UINTS 43904

__global__ __launch_bounds__(256, 1) void lstm_persist(
    const uint32_t* __restrict__ Wg_h, const uint32_t* __restrict__ Wg_l,
    uint32_t* __restrict__ hbH, uint32_t* __restrict__ hbL,   // [2][Bm*Hm/2]
    const float* __restrict__ xg,
    uint32_t* __restrict__ seqH, uint32_t* __restrict__ seqL)
{
    extern __shared__ uint32_t sm[];
    uint32_t* WhS = sm;
    uint32_t* WlS = sm + SW_OFF_WL;
    uint32_t* AhS = sm + SW_OFF_AH;
    uint32_t* AlS = sm + SW_OFF_AL;
    float*    gsS = (float*)(sm + SW_OFF_GS);

    const int tid = threadIdx.x;
    const int wid = tid >> 5, lane = tid & 31;
    const int g = lane >> 2, tig = lane & 3;
    const int wm = wid >> 1, wn = wid & 1;
    const int h0 = blockIdx.x * 8;
    const int K2 = Hm / 2;          // 512 uints per row
    const int HBUF = Bm * Hm / 2;

    // ---- prologue: W slice -> smem (32 rows x 512 uints, hi+lo) ----
#pragma unroll
    for (int i = 0; i < 16; i++) {
        const int u = tid + 256 * i;          // 4096 uint4 units per matrix
        const int r = u >> 7, c = (u & 127) * 4;
        const int grow = ((r >> 3) * Hm + h0 + (r & 7)) * K2;
        *(uint4*)&WhS[r * 516 + c] = *(const uint4*)&Wg_h[grow + c];
        *(uint4*)&WlS[r * 516 + c] = *(const uint4*)&Wg_l[grow + c];
    }

    // ldmatrix bases
    const int lrow = lane & 15, lhalf = lane >> 4;
    const uint32_t aBase  = smemu32(AhS) + (uint32_t)((wm * 16 + lrow) * 272);
    const uint32_t alBase = smemu32(AlS) + (uint32_t)((wm * 16 + lrow) * 272);
    const uint32_t wBase  = smemu32(WhS) + (uint32_t)((wn * 16 + lrow) * 2064);
    const uint32_t wlBase = smemu32(WlS) + (uint32_t)((wn * 16 + lrow) * 2064);

    // epilogue map + register cell state
    const int eb  = tid >> 2;
    const int ejj = (tid & 3) * 2;
    float2 cv = make_float2(0.0f, 0.0f);

    __syncthreads();   // W smem ready

    for (int t = 0; t < Tm; t++) {
        const uint32_t* hinH  = hbH + (t & 1) * HBUF;
        const uint32_t* hinL  = hbL + (t & 1) * HBUF;
        uint32_t*       houtH = hbH + ((t + 1) & 1) * HBUF;
        uint32_t*       houtL = hbL + ((t + 1) & 1) * HBUF;

        float acc[2][4];
#pragma unroll
        for (int p = 0; p < 2; p++)
#pragma unroll
            for (int q = 0; q < 4; q++) acc[p][q] = 0.0f;

        uint4 pH[4], pL[4];
        auto loadG = [&](int kc) {
#pragma unroll
            for (int i = 0; i < 4; i++) {
                const int u = tid + 256 * i;
                const int r = u >> 4, c = (u & 15) * 4;
                pH[i] = __ldcg((const uint4*)&hinH[r * K2 + kc * 64 + c]);
                pL[i] = __ldcg((const uint4*)&hinL[r * K2 + kc * 64 + c]);
            }
        };

        loadG(0);
#pragma unroll 1
        for (int kc = 0; kc < 8; kc++) {
            __syncthreads();
#pragma unroll
            for (int i = 0; i < 4; i++) {
                const int u = tid + 256 * i;
                const int r = u >> 4, c = (u & 15) * 4;
                *(uint4*)&AhS[r * 68 + c] = pH[i];
                *(uint4*)&AlS[r * 68 + c] = pL[i];
            }
            __syncthreads();
            if (kc + 1 < 8) loadG(kc + 1);

#pragma unroll
            for (int k16 = 0; k16 < 8; k16++) {            // FIX: 8 x 16 = 128 elems
                const uint32_t acoff = (uint32_t)((k16 * 2 + lhalf) * 16);
                const uint32_t wcoff = (uint32_t)(((kc * 8 + k16) * 2 + lhalf) * 16);  // FIX
                uint32_t ah0, ah1, ah2, ah3, al0, al1, al2, al3;
                uint32_t bh0, bh1, bh2, bh3, bl0, bl1, bl2, bl3;
                ldsm4(ah0, ah1, ah2, ah3, aBase  + acoff);
                ldsm4(al0, al1, al2, al3, alBase + acoff);
                ldsm4(bh0, bh1, bh2, bh3, wBase  + wcoff);
                ldsm4(bl0, bl1, bl2, bl3, wlBase + wcoff);
                mma_bf16(acc[0], ah0, ah1, ah2, ah3, bh0, bh2);
                mma_bf16(acc[1], ah0, ah1, ah2, ah3, bh1, bh3);
                mma_bf16(acc[0], ah0, ah1, ah2, ah3, bl0, bl2);
                mma_bf16(acc[1], ah0, ah1, ah2, ah3, bl1, bl3);
                mma_bf16(acc[0], al0, al1, al2, al3, bh0, bh2);
                mma_bf16(acc[1], al0, al1, al2, al3, bh1, bh3);
            }
        }

        // stage gate pre-activations
        {
            const int r0 = wm * 16 + g, r1 = r0 + 8;
#pragma unroll
            for (int p = 0; p < 2; p++) {
                const int c = wn * 16 + p * 8 + 2 * tig;
                gsS[r0 * 34 + c] = acc[p][0]; gsS[r0 * 34 + c + 1] = acc[p][1];
                gsS[r1 * 34 + c] = acc[p][2]; gsS[r1 * 34 + c + 1] = acc[p][3];
            }
        }
        __syncthreads();

        // activations + cell update (cell state in registers)
        float gate[4][2];
#pragma unroll
        for (int gt = 0; gt < 4; gt++) {
            const float2 xv = *(const float2*)&xg[(size_t)(eb * Tm + t) * G4 + gt * Hm + h0 + ejj];
            gate[gt][0] = gsS[eb * 34 + 8 * gt + ejj]     + xv.x;
            gate[gt][1] = gsS[eb * 34 + 8 * gt + ejj + 1] + xv.y;
        }
        float hv[2];
#pragma unroll
        for (int e = 0; e < 2; e++) {
            const float iv = sigf(gate[0][e]);
            const float fv = sigf(gate[1][e]);
            const float gv = tanhx(gate[2][e]);
            const float ov = sigf(gate[3][e]);
            const float cc = (e == 0 ? cv.x : cv.y);
            const float cn = fv * cc + iv * gv;
            if (e == 0) cv.x = cn; else cv.y = cn;
            hv[e] = ov * tanhx(cn);
        }

        const __nv_bfloat16 b0 = __float2bfloat16_rn(hv[0]);
        const __nv_bfloat16 b1 = __float2bfloat16_rn(hv[1]);
        const __nv_bfloat16 l0 = __float2bfloat16_rn(hv[0] - __bfloat162float(b0));
        const __nv_bfloat16 l1 = __float2bfloat16_rn(hv[1] - __bfloat162float(b1));
        const uint32_t uhi = (uint32_t)__bfloat16_as_ushort(b0) | ((uint32_t)__bfloat16_as_ushort(b1) << 16);
        const uint32_t ulo = (uint32_t)__bfloat16_as_ushort(l0) | ((uint32_t)__bfloat16_as_ushort(l1) << 16);
        const int hidx = (eb * Hm + h0 + ejj) >> 1;
        houtH[hidx] = uhi;
        houtL[hidx] = ulo;
        if (seqH) {
            const int si = ((eb * Tm + t) * Hm + h0 + ejj) >> 1;
            seqH[si] = uhi;
            seqL[si] = ulo;
        }

        gridbar();   // h_out visible to all CTAs before next step
    }
}

// ---------------------------------------------------------------------------
extern "C" void kernel_launch(void* const* d_in, const int* in_sizes, int n_in,
                              void* d_out, int out_size)
{
    const float* x     = (const float*)d_in[0];
    const float* W_ih0 = (const float*)d_in[1];
    const float* W_hh0 = (const float*)d_in[2];
    const float* b_ih0 = (const float*)d_in[3];
    const float* b_hh0 = (const float*)d_in[4];
    const float* W_ih1 = (const float*)d_in[5];
    const float* W_hh1 = (const float*)d_in[6];
    const float* b_ih1 = (const float*)d_in[7];
    const float* b_hh1 = (const float*)d_in[8];
    const float* fc_w  = (const float*)d_in[9];
    const float* fc_b  = (const float*)d_in[10];
    float* out = (float*)d_out;

    uint32_t *xh, *xl, *sh, *sl, *wih0h, *wih0l, *whh0h, *whh0l;
    uint32_t *wih1h, *wih1l, *whh1h, *whh1l, *fwh, *fwl, *hh, *hl;
    float *xg;
    cudaGetSymbolAddress((void**)&xh, g_xh);       cudaGetSymbolAddress((void**)&xl, g_xl);
    cudaGetSymbolAddress((void**)&sh, g_sh);       cudaGetSymbolAddress((void**)&sl, g_sl);
    cudaGetSymbolAddress((void**)&wih0h, g_wih0h); cudaGetSymbolAddress((void**)&wih0l, g_wih0l);
    cudaGetSymbolAddress((void**)&whh0h, g_whh0h); cudaGetSymbolAddress((void**)&whh0l, g_whh0l);
    cudaGetSymbolAddress((void**)&wih1h, g_wih1h); cudaGetSymbolAddress((void**)&wih1l, g_wih1l);
    cudaGetSymbolAddress((void**)&whh1h, g_whh1h); cudaGetSymbolAddress((void**)&whh1l, g_whh1l);
    cudaGetSymbolAddress((void**)&fwh, g_fwh);     cudaGetSymbolAddress((void**)&fwl, g_fwl);
    cudaGetSymbolAddress((void**)&hh, g_hh);       cudaGetSymbolAddress((void**)&hl, g_hl);
    cudaGetSymbolAddress((void**)&xg, g_xg);

    static bool attrSet = false;
    if (!attrSet) {
        cudaFuncSetAttribute(lstm_persist, cudaFuncAttributeMaxDynamicSharedMemorySize,
                             SMEM_UINTS * 4);
        attrSet = true;
    }

    const int HBUF = Bm * Hm / 2;

    auto splits = [&](const float* s, uint32_t* h, uint32_t* l, int elems) {
        int n2 = elems / 2;
        split2<<<(n2 + 255) / 256, 256>>>(s, h, l, n2);
    };
    splits(x,     xh,    xl,    BT * DIN);
    splits(W_ih0, wih0h, wih0l, G4 * DIN);
    splits(W_hh0, whh0h, whh0l, G4 * Hm);
    splits(W_ih1, wih1h, wih1l, G4 * Hm);
    splits(W_hh1, whh1h, whh1l, G4 * Hm);
    splits(fc_w,  fwh,   fwl,   C_OUT * Hm);

    // ---- layer 0 ----
    cudaMemsetAsync(hh, 0, 2 * HBUF * 4);
    cudaMemsetAsync(hl, 0, 2 * HBUF * 4);
    gemmT<<<dim3(G4 / 128, BT / 128), 256>>>(xh, xl, wih0h, wih0l,
                                             b_ih0, b_hh0, xg, BT, G4, DIN);
    lstm_persist<<<NCTA, 256, SMEM_UINTS * 4>>>(whh0h, whh0l, hh, hl, xg, sh, sl);

    // ---- layer 1 ----
    gemmT<<<dim3(G4 / 128, BT / 128), 256>>>(sh, sl, wih1h, wih1l,
                                             b_ih1, b_hh1, xg, BT, G4, Hm);
    cudaMemsetAsync(hh, 0, 2 * HBUF * 4);
    cudaMemsetAsync(hl, 0, 2 * HBUF * 4);
    lstm_persist<<<NCTA, 256, SMEM_UINTS * 4>>>(whh1h, whh1l, hh, hl, xg,
                                                (uint32_t*)nullptr, (uint32_t*)nullptr);

    // ---- classifier on final hidden state (T even -> buffer 0) ----
    gemmT<<<dim3((C_OUT + 127) / 128, 1), 256>>>(hh, hl, fwh, fwl,
                                                 fc_b, (const float*)nullptr,
                                                 out, Bm, C_OUT, Hm);
}